// round 17
// baseline (speedup 1.0000x reference)
#include <cuda_runtime.h>
#include <math.h>

#define NUM_CLASSES 1000
#define FEAT_DIM    256
#define NROWS       262144
#define ALPHA       0.5f

#define NB 592            // 148 SMs x 4 co-resident (reg cap 64) - REQUIRED for barriers
#define NT 256
#define RPB_F ((NROWS + NB - 1) / NB)     // 443 rows per block (last block 331)

#define TOTAL_WARPS (NB * (NT / 32))      // 4736
#define CHUNK ((NROWS + TOTAL_WARPS - 1) / TOTAL_WARPS)   // 56 (<= 64)

// ---- scratch (device globals; zero-init; self-maintaining across replays) -
__device__ float g_sums[NUM_CLASSES * FEAT_DIM];   // re-zeroed by epilogue
__device__ float g_counts[NUM_CLASSES];
__device__ int   g_tot[NUM_CLASSES];               // re-zeroed by epilogue
__device__ int   g_sorted[NROWS];
__device__ float g_loss;                           // re-zeroed by epilogue
__device__ int   g_cnt[3];                         // sense-reversing barrier state
__device__ int   g_sense[3];                       // (never needs external reset)

// Sense-reversing grid barrier: replay-safe, no reset required.
__device__ __forceinline__ void grid_sync(int slot) {
    __syncthreads();
    if (threadIdx.x == 0) {
        int s = atomicAdd(&g_sense[slot], 0);
        __threadfence();
        int old = atomicAdd(&g_cnt[slot], 1);
        if (old == NB - 1) {
            g_cnt[slot] = 0;
            __threadfence();
            atomicExch(&g_sense[slot], s ^ 1);
        } else {
            while (atomicAdd(&g_sense[slot], 0) == s) __nanosleep(32);
        }
        __threadfence();
    }
    __syncthreads();
}

// Vectorized reduction-add to global (sm_90+)
__device__ __forceinline__ void red_add_v4(float* addr, float4 v) {
    asm volatile("red.global.add.v4.f32 [%0], {%1, %2, %3, %4};"
                 :: "l"(addr), "f"(v.x), "f"(v.y), "f"(v.z), "f"(v.w)
                 : "memory");
}
__device__ __forceinline__ float4 f4add(float4 a, float4 b) {
    return make_float4(a.x + b.x, a.y + b.y, a.z + b.z, a.w + b.w);
}

// ---------------------------------------------------------------------------
// SINGLE kernel: hist -> reservation -> [sync] -> scan+scatter -> [sync] ->
// main fused pass -> [sync] -> finalize epilogue. 592 blocks co-resident.
// ---------------------------------------------------------------------------
__global__ void __launch_bounds__(NT, 4)
cl_all_kernel(const float* __restrict__ x,
              const void*  __restrict__ labels_raw,
              const float* __restrict__ centers,
              float* __restrict__ out) {
    __shared__ int   sh_hist[1024];
    __shared__ int   sh_res[1024];
    __shared__ int   sh_cur[1024];
    __shared__ int   sh_wsum[8];
    __shared__ int   sh_is64;
    __shared__ float s_loss;

    const int t = threadIdx.x;
    const int bid = blockIdx.x;
    const int lane = t & 31;
    const int wid = t >> 5;

    // ================= phase S1: histogram + reservation =================
    #pragma unroll
    for (int j = 0; j < 4; j++) sh_hist[t * 4 + j] = 0;
    if (t == 0) s_loss = 0.0f;
    if (wid == 0) {
        // int64 labels < 1000 -> all odd 32-bit words zero (branch-free OR)
        const int* w = (const int*)labels_raw;
        int v = w[2 * lane + 1] | w[2 * (lane + 32) + 1];
        int any = __any_sync(0xFFFFFFFFu, v != 0);
        if (lane == 0) sh_is64 = !any;
    }
    __syncthreads();
    const int is64 = sh_is64;
    const long long* lab64 = (const long long*)labels_raw;
    const int*       lab32 = (const int*)labels_raw;

    const int rbase = bid * RPB_F;
    const int nrow = (rbase + RPB_F <= NROWS) ? RPB_F : (NROWS - rbase);

    int l0 = -1, l1 = -1;
    if (t < nrow)      l0 = is64 ? (int)lab64[rbase + t] : lab32[rbase + t];
    if (NT + t < nrow) l1 = is64 ? (int)lab64[rbase + NT + t]
                                 : lab32[rbase + NT + t];
    if (l0 >= 0) atomicAdd(&sh_hist[l0], 1);
    if (l1 >= 0) atomicAdd(&sh_hist[l1], 1);
    __syncthreads();
    #pragma unroll
    for (int j = 0; j < 4; j++) {
        int c = t * 4 + j;
        int cnt = sh_hist[c];
        int res = 0;
        if (cnt > 0) res = atomicAdd(&g_tot[c], cnt);   // return = my offset
        sh_res[c] = res;
    }

    grid_sync(0);

    // ============ phase S2: block-local scan of totals + scatter ==========
    {
        int v[4], tsum = 0;
        #pragma unroll
        for (int j = 0; j < 4; j++) {
            int c = t * 4 + j;
            v[j] = (c < NUM_CLASSES) ? __ldcg(&g_tot[c]) : 0;
            tsum += v[j];
        }
        int incl = tsum;
        #pragma unroll
        for (int o = 1; o < 32; o <<= 1) {
            int n = __shfl_up_sync(0xFFFFFFFFu, incl, o);
            if (lane >= o) incl += n;
        }
        if (lane == 31) sh_wsum[wid] = incl;
        __syncthreads();
        if (wid == 0) {
            int ws = (lane < 8) ? sh_wsum[lane] : 0;
            int wincl = ws;
            #pragma unroll
            for (int o = 1; o < 32; o <<= 1) {
                int n = __shfl_up_sync(0xFFFFFFFFu, wincl, o);
                if (lane >= o) wincl += n;
            }
            if (lane < 8) sh_wsum[lane] = wincl - ws;   // exclusive warp prefix
        }
        __syncthreads();
        int run = sh_wsum[wid] + (incl - tsum);          // thread exclusive base
        #pragma unroll
        for (int j = 0; j < 4; j++) {
            int c = t * 4 + j;
            if (c < NUM_CLASSES) {
                if (bid == 0) g_counts[c] = (float)v[j];
                sh_cur[c] = run + sh_res[c];
            }
            run += v[j];
        }
    }
    __syncthreads();
    if (l0 >= 0) {
        int pos = atomicAdd(&sh_cur[l0], 1);
        g_sorted[pos] = (l0 << 18) | (rbase + t);
    }
    if (l1 >= 0) {
        int pos = atomicAdd(&sh_cur[l1], 1);
        g_sorted[pos] = (l1 << 18) | (rbase + NT + t);
    }

    grid_sync(1);

    // ===================== phase M: main fused pass =======================
    const int gwarp = bid * (NT / 32) + wid;
    const int pos0  = gwarp * CHUNK;
    int cnt = NROWS - pos0;
    if (cnt > CHUNK) cnt = CHUNK;
    if (cnt < 0) cnt = 0;

    int ent0 = 0, ent1 = 0;
    if (pos0 < NROWS) {
        if (lane < cnt)      ent0 = g_sorted[pos0 + lane];
        if (32 + lane < cnt) ent1 = g_sorted[pos0 + 32 + lane];
    }

    float loss_acc = 0.0f;
    float4 acc_a = make_float4(0.f, 0.f, 0.f, 0.f);
    float4 acc_b = make_float4(0.f, 0.f, 0.f, 0.f);
    float4 ca = acc_a, cb = acc_b;
    int cur_lbl = -1;

    int i = 0;
    for (; i + 4 <= cnt; i += 4) {
        int lbl[4], row[4];
        #pragma unroll
        for (int r = 0; r < 4; r++) {
            int idx = i + r;
            int e = (idx < 32) ? __shfl_sync(0xFFFFFFFFu, ent0, idx)
                               : __shfl_sync(0xFFFFFFFFu, ent1, idx - 32);
            lbl[r] = e >> 18;
            row[r] = e & 0x3FFFF;
        }
        float4 xa[4], xb[4];
        #pragma unroll
        for (int r = 0; r < 4; r++) {
            const float4* __restrict__ xr =
                (const float4*)(x + (size_t)row[r] * FEAT_DIM);
            xa[r] = __ldcs(xr + lane);
            xb[r] = __ldcs(xr + lane + 32);
        }

        float ss[4];
        #pragma unroll
        for (int r = 0; r < 4; r++) {
            if (lbl[r] != cur_lbl) {
                if (cur_lbl >= 0) {
                    float* b = g_sums + (size_t)cur_lbl * FEAT_DIM;
                    red_add_v4(b + lane * 4, acc_a);
                    red_add_v4(b + 128 + lane * 4, acc_b);
                    acc_a = make_float4(0.f, 0.f, 0.f, 0.f);
                    acc_b = make_float4(0.f, 0.f, 0.f, 0.f);
                }
                const float4* cr = (const float4*)(centers + (size_t)lbl[r] * FEAT_DIM);
                ca = cr[lane]; cb = cr[lane + 32];
                cur_lbl = lbl[r];
            }
            acc_a = f4add(acc_a, xa[r]);
            acc_b = f4add(acc_b, xb[r]);
            float d0 = xa[r].x-ca.x, d1 = xa[r].y-ca.y,
                  d2 = xa[r].z-ca.z, d3 = xa[r].w-ca.w;
            float f0 = xb[r].x-cb.x, f1 = xb[r].y-cb.y,
                  f2 = xb[r].z-cb.z, f3 = xb[r].w-cb.w;
            ss[r] = d0*d0+d1*d1+d2*d2+d3*d3 + f0*f0+f1*f1+f2*f2+f3*f3;
        }

        #pragma unroll
        for (int o = 16; o > 0; o >>= 1) {
            #pragma unroll
            for (int r = 0; r < 4; r++)
                ss[r] += __shfl_xor_sync(0xFFFFFFFFu, ss[r], o);
        }
        if (lane == 0)
            loss_acc += (sqrtf(ss[0]) + sqrtf(ss[1]))
                      + (sqrtf(ss[2]) + sqrtf(ss[3]));
    }

    for (; i < cnt; i++) {
        int e = (i < 32) ? __shfl_sync(0xFFFFFFFFu, ent0, i)
                         : __shfl_sync(0xFFFFFFFFu, ent1, i - 32);
        int lbl = e >> 18, row = e & 0x3FFFF;
        const float4* __restrict__ xr = (const float4*)(x + (size_t)row * FEAT_DIM);
        float4 xa = __ldcs(xr + lane), xb = __ldcs(xr + lane + 32);
        if (lbl != cur_lbl) {
            if (cur_lbl >= 0) {
                float* b = g_sums + (size_t)cur_lbl * FEAT_DIM;
                red_add_v4(b + lane * 4, acc_a);
                red_add_v4(b + 128 + lane * 4, acc_b);
                acc_a = make_float4(0.f, 0.f, 0.f, 0.f);
                acc_b = make_float4(0.f, 0.f, 0.f, 0.f);
            }
            const float4* cr = (const float4*)(centers + (size_t)lbl * FEAT_DIM);
            ca = cr[lane]; cb = cr[lane + 32];
            cur_lbl = lbl;
        }
        acc_a = f4add(acc_a, xa);
        acc_b = f4add(acc_b, xb);
        float d0 = xa.x-ca.x, d1 = xa.y-ca.y, d2 = xa.z-ca.z, d3 = xa.w-ca.w;
        float f0 = xb.x-cb.x, f1 = xb.y-cb.y, f2 = xb.z-cb.z, f3 = xb.w-cb.w;
        float ss = d0*d0+d1*d1+d2*d2+d3*d3 + f0*f0+f1*f1+f2*f2+f3*f3;
        #pragma unroll
        for (int o = 16; o > 0; o >>= 1)
            ss += __shfl_xor_sync(0xFFFFFFFFu, ss, o);
        if (lane == 0) loss_acc += sqrtf(ss);
    }

    if (cur_lbl >= 0) {
        float* b = g_sums + (size_t)cur_lbl * FEAT_DIM;
        red_add_v4(b + lane * 4, acc_a);
        red_add_v4(b + 128 + lane * 4, acc_b);
    }

    if (lane == 0) atomicAdd(&s_loss, loss_acc);
    __syncthreads();
    if (t == 0) atomicAdd(&g_loss, s_loss);

    // ================= phase F: finalize epilogue + resets ================
    grid_sync(2);

    const int gid = bid * NT + t;
    if (gid == 0) { out[0] = g_loss * (0.5f / (float)NROWS); g_loss = 0.0f; }
    if (gid < NUM_CLASSES) g_tot[gid] = 0;
    for (int j = gid; j < NUM_CLASSES * FEAT_DIM; j += NB * NT) {
        int c = j / FEAT_DIM;
        float cn = g_counts[c];
        float cen = centers[j];
        float res = cen;
        if (cn > 0.0f) {
            float mean = g_sums[j] / cn;
            res = cen + ALPHA * (mean - cen);
        }
        out[1 + j] = res;
        g_sums[j] = 0.0f;                 // re-zero for next replay
    }
}

// ---------------------------------------------------------------------------
extern "C" void kernel_launch(void* const* d_in, const int* in_sizes, int n_in,
                              void* d_out, int out_size) {
    const float* x       = (const float*)d_in[0];
    const void*  labels  = d_in[1];
    const float* centers = (const float*)d_in[2];
    float*       out     = (float*)d_out;
    (void)in_sizes; (void)n_in; (void)out_size;

    cl_all_kernel<<<NB, NT>>>(x, labels, centers, out);
}